// round 1
// baseline (speedup 1.0000x reference)
#include <cuda_runtime.h>
#include <math.h>

// Problem constants
// B=8, M=1024, H=512, K=8 heads, D=64, SPAN=1024, MK=2048

// ---------------- scratch (device globals; no allocations allowed) ----------
__device__ float g_Q[64 * 1024 * 64];   // [n=64][m=1024][d=64]
__device__ float g_K[64 * 2048 * 64];   // [n=64][t=2048][d=64]
__device__ float g_V[64 * 2048 * 64];   // [n=64][t=2048][d=64]
__device__ float g_C[8 * 1024 * 512];   // [b][m][h] context before Wo

// ---------------- generic 512-K GEMM: C[R,512] = A[R,512] @ W[512,512] ------
// HEAD=true scatters output into per-head layout [(b*8+head)*T + t][64]
template <bool HEAD>
__global__ void __launch_bounds__(256) gemm512(const float* __restrict__ A,
                                               const float* __restrict__ W,
                                               float* __restrict__ out, int T) {
    __shared__ float Ast[16 * 68];  // A tile transposed: [p][i]
    __shared__ float Ws[16 * 68];   // W tile: [p][j]

    const int tid = threadIdx.x;
    const int ty = tid >> 4, tx = tid & 15;
    const int r0 = ty * 4, c0 = tx * 4;
    const int row0 = blockIdx.x * 64;
    const int col0 = blockIdx.y * 64;

    float acc[4][4] = {};

    for (int kk = 0; kk < 512; kk += 16) {
        {
            int i = tid >> 2;           // 0..63
            int p4 = (tid & 3) * 4;     // 0,4,8,12
            float4 v = *(const float4*)&A[(size_t)(row0 + i) * 512 + kk + p4];
            Ast[(p4 + 0) * 68 + i] = v.x;
            Ast[(p4 + 1) * 68 + i] = v.y;
            Ast[(p4 + 2) * 68 + i] = v.z;
            Ast[(p4 + 3) * 68 + i] = v.w;
        }
        {
            int p = tid >> 4;
            int j4 = (tid & 15) * 4;
            float4 v = *(const float4*)&W[(size_t)(kk + p) * 512 + col0 + j4];
            *(float4*)&Ws[p * 68 + j4] = v;
        }
        __syncthreads();
#pragma unroll
        for (int p = 0; p < 16; p++) {
            float4 a4 = *(float4*)&Ast[p * 68 + r0];
            float4 b4 = *(float4*)&Ws[p * 68 + c0];
            float a[4] = {a4.x, a4.y, a4.z, a4.w};
            float b[4] = {b4.x, b4.y, b4.z, b4.w};
#pragma unroll
            for (int i = 0; i < 4; i++)
#pragma unroll
                for (int j = 0; j < 4; j++) acc[i][j] += a[i] * b[j];
        }
        __syncthreads();
    }

    if (HEAD) {
        int head = col0 >> 6;
#pragma unroll
        for (int i = 0; i < 4; i++) {
            int row = row0 + r0 + i;
            int b = row / T, t = row - b * T;
            size_t base = (((size_t)(b * 8 + head) * T + t) * 64) + c0;
            *(float4*)&out[base] =
                make_float4(acc[i][0], acc[i][1], acc[i][2], acc[i][3]);
        }
    } else {
#pragma unroll
        for (int i = 0; i < 4; i++) {
            int row = row0 + r0 + i;
            *(float4*)&out[(size_t)row * 512 + col0 + c0] =
                make_float4(acc[i][0], acc[i][1], acc[i][2], acc[i][3]);
        }
    }
}

// ---------------- fused banded attention ------------------------------------
// For query m: scores(s) = (q_m . k_{m+s} + q_m . E[:,s]) / 8 , s in [0,1024)
// softmax over s, out = sum_s p(s) * v_{m+s}. No masking needed (window always full).
// Block: 64 queries (one m-tile) of one head-batch n. 256 threads, 4x4 microtiles.
__global__ void __launch_bounds__(256) attn_kernel(const float* __restrict__ Q,
                                                   const float* __restrict__ Kg,
                                                   const float* __restrict__ Vg,
                                                   const float* __restrict__ Eg,
                                                   float* __restrict__ Cg) {
    extern __shared__ float sm[];
    float* Qt = sm;                 // [d=64][mi=64] pad 68
    float* Kt = Qt + 64 * 68;       // [d=64][kr=128] pad 132
    float* Vs = Kt + 64 * 132;      // [kr=128][d=64] pad 68
    float* Es = Vs + 128 * 68;      // [d=64][sj=64] pad 68
    float* Pt = Es + 64 * 68;       // [sj=64][mi=64] pad 68

    const int tid = threadIdx.x;
    const int ty = tid >> 4, tx = tid & 15;
    const int r0 = ty * 4, c0 = tx * 4;
    const int rc = r0 + c0;
    const int n = blockIdx.y;
    const int m0 = blockIdx.x * 64;

    // Load Q tile transposed (once)
    for (int f = tid; f < 1024; f += 256) {
        int mi = f >> 4;
        int d4 = (f & 15) * 4;
        float4 v = *(const float4*)&Q[((size_t)n * 1024 + m0 + mi) * 64 + d4];
        Qt[(d4 + 0) * 68 + mi] = v.x;
        Qt[(d4 + 1) * 68 + mi] = v.y;
        Qt[(d4 + 2) * 68 + mi] = v.z;
        Qt[(d4 + 3) * 68 + mi] = v.w;
    }

    float O[4][4] = {};
    float mrun[4] = {-1e30f, -1e30f, -1e30f, -1e30f};
    float lrun[4] = {0.f, 0.f, 0.f, 0.f};

    const float SC = 0.125f * 1.4426950408889634f;  // 1/sqrt(64) * log2(e)

    for (int s0 = 0; s0 < 1024; s0 += 64) {
        const int kp0 = m0 + s0;  // first key row this chunk (max 2047-127 ok)
        __syncthreads();          // prior PV done before overwriting K/V/E
        // Load K chunk transposed: 128 key rows
        for (int f = tid; f < 2048; f += 256) {
            int kr = f >> 4;
            int d4 = (f & 15) * 4;
            float4 v =
                *(const float4*)&Kg[((size_t)n * 2048 + kp0 + kr) * 64 + d4];
            Kt[(d4 + 0) * 132 + kr] = v.x;
            Kt[(d4 + 1) * 132 + kr] = v.y;
            Kt[(d4 + 2) * 132 + kr] = v.z;
            Kt[(d4 + 3) * 132 + kr] = v.w;
        }
        // Load V chunk row-major
        for (int f = tid; f < 2048; f += 256) {
            int kr = f >> 4;
            int d4 = (f & 15) * 4;
            float4 v =
                *(const float4*)&Vg[((size_t)n * 2048 + kp0 + kr) * 64 + d4];
            *(float4*)&Vs[kr * 68 + d4] = v;
        }
        // Load E chunk: Es[d][sj] = E[d, s0+sj]
        for (int f = tid; f < 1024; f += 256) {
            int d = f >> 4;
            int s4 = (f & 15) * 4;
            float4 v = *(const float4*)&Eg[(size_t)d * 1024 + s0 + s4];
            *(float4*)&Es[d * 68 + s4] = v;
        }
        __syncthreads();

        // S[i][j] = sum_d q[r0+i][d] * ( k[(r0+i)+(c0+j)][d] + E[d][c0+j] )
        float acc[4][4] = {};
#pragma unroll 4
        for (int d = 0; d < 64; d++) {
            float4 q4 = *(float4*)&Qt[d * 68 + r0];
            float4 ka = *(float4*)&Kt[d * 132 + rc];
            float4 kb = *(float4*)&Kt[d * 132 + rc + 4];
            float4 e4 = *(float4*)&Es[d * 68 + c0];
            float q[4] = {q4.x, q4.y, q4.z, q4.w};
            float k[8] = {ka.x, ka.y, ka.z, ka.w, kb.x, kb.y, kb.z, kb.w};
            float e[4] = {e4.x, e4.y, e4.z, e4.w};
#pragma unroll
            for (int i = 0; i < 4; i++)
#pragma unroll
                for (int j = 0; j < 4; j++)
                    acc[i][j] += q[i] * (k[i + j] + e[j]);
        }

        // online softmax (scaled log2 domain)
#pragma unroll
        for (int i = 0; i < 4; i++) {
            float mc = fmaxf(fmaxf(acc[i][0], acc[i][1]),
                             fmaxf(acc[i][2], acc[i][3]));
#pragma unroll
            for (int off = 1; off < 16; off <<= 1)
                mc = fmaxf(mc, __shfl_xor_sync(0xffffffffu, mc, off));
            mc *= SC;
            float mn = fmaxf(mrun[i], mc);
            float alpha = exp2f(mrun[i] - mn);
            float p[4];
            float rs = 0.f;
#pragma unroll
            for (int j = 0; j < 4; j++) {
                p[j] = exp2f(acc[i][j] * SC - mn);
                rs += p[j];
            }
#pragma unroll
            for (int off = 1; off < 16; off <<= 1)
                rs += __shfl_xor_sync(0xffffffffu, rs, off);
            lrun[i] = lrun[i] * alpha + rs;
            mrun[i] = mn;
#pragma unroll
            for (int j = 0; j < 4; j++) O[i][j] *= alpha;
#pragma unroll
            for (int j = 0; j < 4; j++) Pt[(c0 + j) * 68 + r0 + i] = p[j];
        }
        __syncthreads();

        // O[i][dj] += sum_sj P[r0+i][sj] * V[(r0+i)+sj][dj]
#pragma unroll 2
        for (int sj = 0; sj < 64; sj++) {
            float4 p4 = *(float4*)&Pt[sj * 68 + r0];
            float p[4] = {p4.x, p4.y, p4.z, p4.w};
#pragma unroll
            for (int i = 0; i < 4; i++) {
                float4 v4 = *(float4*)&Vs[(r0 + i + sj) * 68 + c0];
                O[i][0] += p[i] * v4.x;
                O[i][1] += p[i] * v4.y;
                O[i][2] += p[i] * v4.z;
                O[i][3] += p[i] * v4.w;
            }
        }
    }

    // epilogue: normalize & write context in [B,M,H] layout
    const int b = n >> 3, kh = n & 7;
#pragma unroll
    for (int i = 0; i < 4; i++) {
        float inv = 1.0f / lrun[i];
        size_t base = ((size_t)b * 1024 + m0 + r0 + i) * 512 + kh * 64 + c0;
        *(float4*)&Cg[base] = make_float4(O[i][0] * inv, O[i][1] * inv,
                                          O[i][2] * inv, O[i][3] * inv);
    }
}

// ---------------- launcher ---------------------------------------------------
extern "C" void kernel_launch(void* const* d_in, const int* in_sizes, int n_in,
                              void* d_out, int out_size) {
    const float* query = (const float*)d_in[0];  // [8,1024,512]
    const float* key = (const float*)d_in[1];    // [8,2048,512]
    const float* value = (const float*)d_in[2];  // [8,2048,512]
    const float* pos = (const float*)d_in[3];    // [64,1024]
    const float* Wq = (const float*)d_in[4];
    const float* Wk = (const float*)d_in[5];
    const float* Wv = (const float*)d_in[6];
    const float* Wo = (const float*)d_in[7];
    float* out = (float*)d_out;

    float *Qp, *Kp, *Vp, *Cp;
    cudaGetSymbolAddress((void**)&Qp, g_Q);
    cudaGetSymbolAddress((void**)&Kp, g_K);
    cudaGetSymbolAddress((void**)&Vp, g_V);
    cudaGetSymbolAddress((void**)&Cp, g_C);

    // projections into head layouts
    gemm512<true><<<dim3(128, 8), 256>>>(query, Wq, Qp, 1024);
    gemm512<true><<<dim3(256, 8), 256>>>(key, Wk, Kp, 2048);
    gemm512<true><<<dim3(256, 8), 256>>>(value, Wv, Vp, 2048);

    // fused banded attention
    const int smem_bytes = (64 * 68 + 64 * 132 + 128 * 68 + 64 * 68 + 64 * 68) *
                           (int)sizeof(float);  // 120832
    cudaFuncSetAttribute(attn_kernel, cudaFuncAttributeMaxDynamicSharedMemorySize,
                         smem_bytes);
    attn_kernel<<<dim3(16, 64), 256, smem_bytes>>>(Qp, Kp, Vp, pos, Cp);

    // output projection (plain layout)
    gemm512<false><<<dim3(128, 8), 256>>>(Cp, Wo, out, 1024);
}

// round 3
// speedup vs baseline: 1.5166x; 1.5166x over previous
#include <cuda_runtime.h>
#include <cuda_bf16.h>
#include <stdint.h>
#include <math.h>

// B=8, M=1024, H=512, K=8 heads, D=64, SPAN=1024, MK=2048
#define DINLINE __device__ __forceinline__

// ---------------- scratch ----------------------------------------------------
__device__ __nv_bfloat16 g_Qh[64 * 1024 * 64];
__device__ __nv_bfloat16 g_Ql[64 * 1024 * 64];
__device__ __nv_bfloat16 g_Kh[64 * 2048 * 64];
__device__ __nv_bfloat16 g_Kl[64 * 2048 * 64];
__device__ __nv_bfloat16 g_Vh[64 * 2048 * 64];
__device__ __nv_bfloat16 g_Vl[64 * 2048 * 64];
__device__ float g_C[8 * 1024 * 512];

// ---------------- helpers ----------------------------------------------------
DINLINE void mma_bf16(float c[4], uint32_t a0, uint32_t a1, uint32_t a2,
                      uint32_t a3, uint32_t b0, uint32_t b1) {
    asm volatile(
        "mma.sync.aligned.m16n8k16.row.col.f32.bf16.bf16.f32 "
        "{%0,%1,%2,%3}, {%4,%5,%6,%7}, {%8,%9}, {%0,%1,%2,%3};\n"
        : "+f"(c[0]), "+f"(c[1]), "+f"(c[2]), "+f"(c[3])
        : "r"(a0), "r"(a1), "r"(a2), "r"(a3), "r"(b0), "r"(b1));
}

DINLINE void split_bf(float x, __nv_bfloat16& h, __nv_bfloat16& l) {
    h = __float2bfloat16_rn(x);
    l = __float2bfloat16_rn(x - __bfloat162float(h));
}

DINLINE void st_bf2(__nv_bfloat16* p, __nv_bfloat16 a, __nv_bfloat16 b) {
    __nv_bfloat162 t;
    t.x = a;
    t.y = b;
    *(__nv_bfloat162*)p = t;
}

// ---------------- bf16x3 GEMM: C[R,512] = A[R,512] @ W[512,512] ---------------
// EPI=0: fp32 plain out. EPI=1: head-scatter bf16 hi/lo out.
template <int EPI>
__global__ void __launch_bounds__(256, 1) gemm_tc(
    const float* __restrict__ A, const float* __restrict__ W,
    float* __restrict__ outF, __nv_bfloat16* __restrict__ outH,
    __nv_bfloat16* __restrict__ outL, int T) {
    constexpr int AS = 42;  // smem row stride (bf16)
    __shared__ __nv_bfloat16 Ah[128 * AS], Al[128 * AS];
    __shared__ __nv_bfloat16 Bh[128 * AS], Bl[128 * AS];

    const int tid = threadIdx.x;
    const int lane = tid & 31, wid = tid >> 5;
    const int wm = wid >> 2, wn = wid & 3;  // 2 x 4 warps
    const int row0 = blockIdx.x * 128, col0 = blockIdx.y * 128;
    const int g = lane >> 2, t2 = (lane & 3) * 2;

    float acc[4][4][4] = {};

    for (int kk = 0; kk < 512; kk += 32) {
        // A tile 128x32 fp32 -> split
        {
            int r = tid >> 3, kq = (tid & 7) * 4;
#pragma unroll
            for (int it = 0; it < 4; it++, r += 32) {
                float4 v = *(const float4*)&A[(size_t)(row0 + r) * 512 + kk + kq];
                __nv_bfloat16 h0, l0, h1, l1, h2, l2, h3, l3;
                split_bf(v.x, h0, l0);
                split_bf(v.y, h1, l1);
                split_bf(v.z, h2, l2);
                split_bf(v.w, h3, l3);
                st_bf2(&Ah[r * AS + kq], h0, h1);
                st_bf2(&Ah[r * AS + kq + 2], h2, h3);
                st_bf2(&Al[r * AS + kq], l0, l1);
                st_bf2(&Al[r * AS + kq + 2], l2, l3);
            }
        }
        // B tile 32x128 fp32 -> split, transposed store [n][k]
        {
            int k = tid >> 5, c4 = (tid & 31) * 4;
#pragma unroll
            for (int it = 0; it < 4; it++, k += 8) {
                float4 v = *(const float4*)&W[(size_t)(kk + k) * 512 + col0 + c4];
                __nv_bfloat16 h, l;
                split_bf(v.x, h, l); Bh[(c4 + 0) * AS + k] = h; Bl[(c4 + 0) * AS + k] = l;
                split_bf(v.y, h, l); Bh[(c4 + 1) * AS + k] = h; Bl[(c4 + 1) * AS + k] = l;
                split_bf(v.z, h, l); Bh[(c4 + 2) * AS + k] = h; Bl[(c4 + 2) * AS + k] = l;
                split_bf(v.w, h, l); Bh[(c4 + 3) * AS + k] = h; Bl[(c4 + 3) * AS + k] = l;
            }
        }
        __syncthreads();
#pragma unroll
        for (int ks = 0; ks < 32; ks += 16) {
            uint32_t ah[4][4], al[4][4], bh[4][2], bl[4][2];
#pragma unroll
            for (int mf = 0; mf < 4; mf++) {
                int rb = wm * 64 + mf * 16 + g;
                ah[mf][0] = *(uint32_t*)&Ah[rb * AS + ks + t2];
                ah[mf][1] = *(uint32_t*)&Ah[(rb + 8) * AS + ks + t2];
                ah[mf][2] = *(uint32_t*)&Ah[rb * AS + ks + 8 + t2];
                ah[mf][3] = *(uint32_t*)&Ah[(rb + 8) * AS + ks + 8 + t2];
                al[mf][0] = *(uint32_t*)&Al[rb * AS + ks + t2];
                al[mf][1] = *(uint32_t*)&Al[(rb + 8) * AS + ks + t2];
                al[mf][2] = *(uint32_t*)&Al[rb * AS + ks + 8 + t2];
                al[mf][3] = *(uint32_t*)&Al[(rb + 8) * AS + ks + 8 + t2];
            }
#pragma unroll
            for (int nf = 0; nf < 4; nf++) {
                int cb = wn * 32 + nf * 8 + g;
                bh[nf][0] = *(uint32_t*)&Bh[cb * AS + ks + t2];
                bh[nf][1] = *(uint32_t*)&Bh[cb * AS + ks + 8 + t2];
                bl[nf][0] = *(uint32_t*)&Bl[cb * AS + ks + t2];
                bl[nf][1] = *(uint32_t*)&Bl[cb * AS + ks + 8 + t2];
            }
#pragma unroll
            for (int mf = 0; mf < 4; mf++)
#pragma unroll
                for (int nf = 0; nf < 4; nf++) {
                    mma_bf16(acc[mf][nf], ah[mf][0], ah[mf][1], ah[mf][2],
                             ah[mf][3], bh[nf][0], bh[nf][1]);
                    mma_bf16(acc[mf][nf], ah[mf][0], ah[mf][1], ah[mf][2],
                             ah[mf][3], bl[nf][0], bl[nf][1]);
                    mma_bf16(acc[mf][nf], al[mf][0], al[mf][1], al[mf][2],
                             al[mf][3], bh[nf][0], bh[nf][1]);
                }
        }
        __syncthreads();
    }

    // epilogue
#pragma unroll
    for (int mf = 0; mf < 4; mf++) {
#pragma unroll
        for (int nf = 0; nf < 4; nf++) {
            int rr = row0 + wm * 64 + mf * 16 + g;
            int cc = col0 + wn * 32 + nf * 8 + t2;
            if (EPI == 0) {
                *(float2*)&outF[(size_t)rr * 512 + cc] =
                    make_float2(acc[mf][nf][0], acc[mf][nf][1]);
                *(float2*)&outF[(size_t)(rr + 8) * 512 + cc] =
                    make_float2(acc[mf][nf][2], acc[mf][nf][3]);
            } else {
                int head = cc >> 6, d = cc & 63;
#pragma unroll
                for (int rh = 0; rh < 2; rh++) {
                    int grow = rr + rh * 8;
                    int b = grow / T, t = grow - b * T;
                    size_t idx = (((size_t)(b * 8 + head) * T + t) << 6) + d;
                    __nv_bfloat16 h0, l0, h1, l1;
                    split_bf(acc[mf][nf][rh * 2 + 0], h0, l0);
                    split_bf(acc[mf][nf][rh * 2 + 1], h1, l1);
                    st_bf2(&outH[idx], h0, h1);
                    st_bf2(&outL[idx], l0, l1);
                }
            }
        }
    }
}

// ---------------- fused banded attention (tensor core) ------------------------
__global__ void __launch_bounds__(256, 1) attn_tc(
    const __nv_bfloat16* __restrict__ Qh, const __nv_bfloat16* __restrict__ Ql,
    const __nv_bfloat16* __restrict__ Kh_, const __nv_bfloat16* __restrict__ Kl_,
    const __nv_bfloat16* __restrict__ Vh_, const __nv_bfloat16* __restrict__ Vl_,
    const float* __restrict__ Eg, float* __restrict__ Cg) {
    constexpr int QS = 72, KS = 72, ES = 72, VS = 132, PS = 132, SS = 132,
                  QES = 68;
    extern __shared__ char smraw[];
    __nv_bfloat16* Qsh = (__nv_bfloat16*)smraw;
    __nv_bfloat16* Qsl = Qsh + 64 * QS;
    __nv_bfloat16* Ksh = Qsl + 64 * QS;
    __nv_bfloat16* Ksl = Ksh + 128 * KS;
    __nv_bfloat16* Esh = Ksl + 128 * KS;
    __nv_bfloat16* Esl = Esh + 64 * ES;
    __nv_bfloat16* Vsh = Esl + 64 * ES;  // [d][key]
    __nv_bfloat16* Vsl = Vsh + 64 * VS;
    __nv_bfloat16* Psh = Vsl + 64 * VS;  // [m][key]
    __nv_bfloat16* Psl = Psh + 64 * PS;
    float* Ss = (float*)(Psl + 64 * PS);  // [m][key]
    float* QEs = Ss + 64 * SS;            // [m][s]
    float* mrow = QEs + 64 * QES;
    float* lrow = mrow + 64;
    float* arow = lrow + 64;

    const int tid = threadIdx.x, lane = tid & 31, wid = tid >> 5;
    const int wm = wid >> 2, wn = wid & 3;  // 2 x 4 warps
    const int g = lane >> 2, t2 = (lane & 3) * 2;
    const int n = blockIdx.y, m0 = blockIdx.x * 64;
    const float SCl2 = 0.125f * 1.4426950408889634f;

    // load Q tile (once)
    {
        const uint4* sh = (const uint4*)(Qh + (((size_t)n * 1024 + m0) << 6));
        const uint4* sl = (const uint4*)(Ql + (((size_t)n * 1024 + m0) << 6));
        for (int f = tid; f < 512; f += 256) {
            int m = f >> 3, j = f & 7;
            ((uint4*)(Qsh + m * QS))[j] = sh[f];
            ((uint4*)(Qsl + m * QS))[j] = sl[f];
        }
    }
    if (tid < 64) {
        mrow[tid] = -1e30f;
        lrow[tid] = 0.f;
    }
    // zero P (band overwritten every chunk; outside-band stays 0)
    for (int f = tid; f < 64 * PS / 2; f += 256) {
        ((uint32_t*)Psh)[f] = 0u;
        ((uint32_t*)Psl)[f] = 0u;
    }

    float o[2][2][4] = {};

    for (int c = 0; c < 16; c++) {
        const int s0 = c * 64;
        const size_t kbase = ((size_t)n * 2048 + m0 + s0) << 6;
        __syncthreads();
        // K chunk: 128 rows x 64 bf16 (hi/lo)
        {
            const uint4* sh = (const uint4*)(Kh_ + kbase);
            const uint4* sl = (const uint4*)(Kl_ + kbase);
            for (int f = tid; f < 1024; f += 256) {
                int kr = f >> 3, j = f & 7;
                ((uint4*)(Ksh + kr * KS))[j] = sh[f];
                ((uint4*)(Ksl + kr * KS))[j] = sl[f];
            }
        }
        // V chunk transposed: Vs[d][key]
        {
            int d2 = tid & 31;
#pragma unroll
            for (int it = 0; it < 8; it++) {
                int key = (((tid >> 5) + it * 8) << 1);
                uint32_t va = *(const uint32_t*)(Vh_ + kbase + (size_t)key * 64 + d2 * 2);
                uint32_t vb = *(const uint32_t*)(Vh_ + kbase + (size_t)(key + 1) * 64 + d2 * 2);
                __nv_bfloat162 a2 = *(__nv_bfloat162*)&va;
                __nv_bfloat162 b2 = *(__nv_bfloat162*)&vb;
                st_bf2(&Vsh[(2 * d2) * VS + key], a2.x, b2.x);
                st_bf2(&Vsh[(2 * d2 + 1) * VS + key], a2.y, b2.y);
                uint32_t wa = *(const uint32_t*)(Vl_ + kbase + (size_t)key * 64 + d2 * 2);
                uint32_t wb = *(const uint32_t*)(Vl_ + kbase + (size_t)(key + 1) * 64 + d2 * 2);
                __nv_bfloat162 c2 = *(__nv_bfloat162*)&wa;
                __nv_bfloat162 e2 = *(__nv_bfloat162*)&wb;
                st_bf2(&Vsl[(2 * d2) * VS + key], c2.x, e2.x);
                st_bf2(&Vsl[(2 * d2 + 1) * VS + key], c2.y, e2.y);
            }
        }
        // E chunk transposed + split: Es[s][d]
#pragma unroll
        for (int it = 0; it < 16; it++) {
            int f = tid + it * 256;
            int s = f & 63, d = f >> 6;
            float e = Eg[d * 1024 + s0 + s];
            __nv_bfloat16 h, l;
            split_bf(e, h, l);
            Esh[s * ES + d] = h;
            Esl[s * ES + d] = l;
        }
        __syncthreads();

        // ---- QK (64x128) + QE (64x64) MMAs ----
        float sAcc[2][4][4] = {};
        float qeAcc[2][2][4] = {};
#pragma unroll
        for (int ks = 0; ks < 64; ks += 16) {
            uint32_t ah[2][4], al[2][4];
#pragma unroll
            for (int mf = 0; mf < 2; mf++) {
                int rb = wm * 32 + mf * 16 + g;
                ah[mf][0] = *(uint32_t*)&Qsh[rb * QS + ks + t2];
                ah[mf][1] = *(uint32_t*)&Qsh[(rb + 8) * QS + ks + t2];
                ah[mf][2] = *(uint32_t*)&Qsh[rb * QS + ks + 8 + t2];
                ah[mf][3] = *(uint32_t*)&Qsh[(rb + 8) * QS + ks + 8 + t2];
                al[mf][0] = *(uint32_t*)&Qsl[rb * QS + ks + t2];
                al[mf][1] = *(uint32_t*)&Qsl[(rb + 8) * QS + ks + t2];
                al[mf][2] = *(uint32_t*)&Qsl[rb * QS + ks + 8 + t2];
                al[mf][3] = *(uint32_t*)&Qsl[(rb + 8) * QS + ks + 8 + t2];
            }
#pragma unroll
            for (int nf = 0; nf < 4; nf++) {
                int cb = wn * 32 + nf * 8 + g;
                uint32_t kb0 = *(uint32_t*)&Ksh[cb * KS + ks + t2];
                uint32_t kb1 = *(uint32_t*)&Ksh[cb * KS + ks + 8 + t2];
                uint32_t kl0 = *(uint32_t*)&Ksl[cb * KS + ks + t2];
                uint32_t kl1 = *(uint32_t*)&Ksl[cb * KS + ks + 8 + t2];
#pragma unroll
                for (int mf = 0; mf < 2; mf++) {
                    mma_bf16(sAcc[mf][nf], ah[mf][0], ah[mf][1], ah[mf][2],
                             ah[mf][3], kb0, kb1);
                    mma_bf16(sAcc[mf][nf], ah[mf][0], ah[mf][1], ah[mf][2],
                             ah[mf][3], kl0, kl1);
                    mma_bf16(sAcc[mf][nf], al[mf][0], al[mf][1], al[mf][2],
                             al[mf][3], kb0, kb1);
                }
            }
#pragma unroll
            for (int nf = 0; nf < 2; nf++) {
                int cb = wn * 16 + nf * 8 + g;
                uint32_t eb0 = *(uint32_t*)&Esh[cb * ES + ks + t2];
                uint32_t eb1 = *(uint32_t*)&Esh[cb * ES + ks + 8 + t2];
                uint32_t el0 = *(uint32_t*)&Esl[cb * ES + ks + t2];
                uint32_t el1 = *(uint32_t*)&Esl[cb * ES + ks + 8 + t2];
#pragma unroll
                for (int mf = 0; mf < 2; mf++) {
                    mma_bf16(qeAcc[mf][nf], ah[mf][0], ah[mf][1], ah[mf][2],
                             ah[mf][3], eb0, eb1);
                    mma_bf16(qeAcc[mf][nf], ah[mf][0], ah[mf][1], ah[mf][2],
                             ah[mf][3], el0, el1);
                    mma_bf16(qeAcc[mf][nf], al[mf][0], al[mf][1], al[mf][2],
                             al[mf][3], eb0, eb1);
                }
            }
        }
        // write S, QE to smem
#pragma unroll
        for (int mf = 0; mf < 2; mf++) {
            int r = wm * 32 + mf * 16 + g;
#pragma unroll
            for (int nf = 0; nf < 4; nf++) {
                int cc = wn * 32 + nf * 8 + t2;
                *(float2*)&Ss[r * SS + cc] =
                    make_float2(sAcc[mf][nf][0], sAcc[mf][nf][1]);
                *(float2*)&Ss[(r + 8) * SS + cc] =
                    make_float2(sAcc[mf][nf][2], sAcc[mf][nf][3]);
            }
#pragma unroll
            for (int nf = 0; nf < 2; nf++) {
                int cc = wn * 16 + nf * 8 + t2;
                *(float2*)&QEs[r * QES + cc] =
                    make_float2(qeAcc[mf][nf][0], qeAcc[mf][nf][1]);
                *(float2*)&QEs[(r + 8) * QES + cc] =
                    make_float2(qeAcc[mf][nf][2], qeAcc[mf][nf][3]);
            }
        }
        __syncthreads();

        // ---- online softmax over the valid band ----
        {
            int row = tid >> 2, gq = tid & 3;
            float z[16];
            float mx = -1e30f;
#pragma unroll
            for (int t = 0; t < 16; t++) {
                int js = gq * 16 + t;
                z[t] = Ss[row * SS + row + js] + QEs[row * QES + js];
                mx = fmaxf(mx, z[t]);
            }
            mx = fmaxf(mx, __shfl_xor_sync(0xffffffffu, mx, 1));
            mx = fmaxf(mx, __shfl_xor_sync(0xffffffffu, mx, 2));
            float mold = mrow[row];
            float mn = fmaxf(mold, mx * SCl2);
            float ssum = 0.f;
#pragma unroll
            for (int t = 0; t < 16; t++) {
                float p = exp2f(z[t] * SCl2 - mn);
                ssum += p;
                __nv_bfloat16 h, l;
                split_bf(p, h, l);
                int js = gq * 16 + t;
                Psh[row * PS + row + js] = h;
                Psl[row * PS + row + js] = l;
            }
            ssum += __shfl_xor_sync(0xffffffffu, ssum, 1);
            ssum += __shfl_xor_sync(0xffffffffu, ssum, 2);
            if (gq == 0) {
                float a = exp2f(mold - mn);
                arow[row] = a;
                lrow[row] = lrow[row] * a + ssum;
                mrow[row] = mn;
            }
        }
        __syncthreads();

        // ---- rescale O and accumulate PV ----
#pragma unroll
        for (int mf = 0; mf < 2; mf++) {
            int r = wm * 32 + mf * 16 + g;
            float a0 = arow[r], a1 = arow[r + 8];
#pragma unroll
            for (int nf = 0; nf < 2; nf++) {
                o[mf][nf][0] *= a0;
                o[mf][nf][1] *= a0;
                o[mf][nf][2] *= a1;
                o[mf][nf][3] *= a1;
            }
        }
#pragma unroll
        for (int ks = 0; ks < 128; ks += 16) {
            uint32_t ph[2][4], pl[2][4];
#pragma unroll
            for (int mf = 0; mf < 2; mf++) {
                int rb = wm * 32 + mf * 16 + g;
                ph[mf][0] = *(uint32_t*)&Psh[rb * PS + ks + t2];
                ph[mf][1] = *(uint32_t*)&Psh[(rb + 8) * PS + ks + t2];
                ph[mf][2] = *(uint32_t*)&Psh[rb * PS + ks + 8 + t2];
                ph[mf][3] = *(uint32_t*)&Psh[(rb + 8) * PS + ks + 8 + t2];
                pl[mf][0] = *(uint32_t*)&Psl[rb * PS + ks + t2];
                pl[mf][1] = *(uint32_t*)&Psl[(rb + 8) * PS + ks + t2];
                pl[mf][2] = *(uint32_t*)&Psl[rb * PS + ks + 8 + t2];
                pl[mf][3] = *(uint32_t*)&Psl[(rb + 8) * PS + ks + 8 + t2];
            }
#pragma unroll
            for (int nf = 0; nf < 2; nf++) {
                int cb = wn * 16 + nf * 8 + g;
                uint32_t vh0 = *(uint32_t*)&Vsh[cb * VS + ks + t2];
                uint32_t vh1 = *(uint32_t*)&Vsh[cb * VS + ks + 8 + t2];
                uint32_t vl0 = *(uint32_t*)&Vsl[cb * VS + ks + t2];
                uint32_t vl1 = *(uint32_t*)&Vsl[cb * VS + ks + 8 + t2];
#pragma unroll
                for (int mf = 0; mf < 2; mf++) {
                    mma_bf16(o[mf][nf], ph[mf][0], ph[mf][1], ph[mf][2],
                             ph[mf][3], vh0, vh1);
                    mma_bf16(o[mf][nf], ph[mf][0], ph[mf][1], ph[mf][2],
                             ph[mf][3], vl0, vl1);
                    mma_bf16(o[mf][nf], pl[mf][0], pl[mf][1], pl[mf][2],
                             pl[mf][3], vh0, vh1);
                }
            }
        }
    }

    __syncthreads();
    // epilogue: normalize, write context fp32 [B,M,H]
    const int b = n >> 3, kh = n & 7;
#pragma unroll
    for (int mf = 0; mf < 2; mf++) {
        int r = wm * 32 + mf * 16 + g;
        float i0 = 1.0f / lrow[r];
        float i1 = 1.0f / lrow[r + 8];
#pragma unroll
        for (int nf = 0; nf < 2; nf++) {
            int cc = kh * 64 + wn * 16 + nf * 8 + t2;
            size_t base = ((size_t)b * 1024 + m0 + r) * 512 + cc;
            *(float2*)&Cg[base] =
                make_float2(o[mf][nf][0] * i0, o[mf][nf][1] * i0);
            *(float2*)&Cg[base + 8 * 512] =
                make_float2(o[mf][nf][2] * i1, o[mf][nf][3] * i1);
        }
    }
}

// ---------------- launcher ----------------------------------------------------
extern "C" void kernel_launch(void* const* d_in, const int* in_sizes, int n_in,
                              void* d_out, int out_size) {
    const float* query = (const float*)d_in[0];
    const float* key = (const float*)d_in[1];
    const float* value = (const float*)d_in[2];
    const float* pos = (const float*)d_in[3];
    const float* Wq = (const float*)d_in[4];
    const float* Wk = (const float*)d_in[5];
    const float* Wv = (const float*)d_in[6];
    const float* Wo = (const float*)d_in[7];
    float* out = (float*)d_out;

    __nv_bfloat16 *qh, *ql, *kh, *kl, *vh, *vl;
    float* cptr;
    cudaGetSymbolAddress((void**)&qh, g_Qh);
    cudaGetSymbolAddress((void**)&ql, g_Ql);
    cudaGetSymbolAddress((void**)&kh, g_Kh);
    cudaGetSymbolAddress((void**)&kl, g_Kl);
    cudaGetSymbolAddress((void**)&vh, g_Vh);
    cudaGetSymbolAddress((void**)&vl, g_Vl);
    cudaGetSymbolAddress((void**)&cptr, g_C);

    gemm_tc<1><<<dim3(64, 4), 256>>>(query, Wq, nullptr, qh, ql, 1024);
    gemm_tc<1><<<dim3(128, 4), 256>>>(key, Wk, nullptr, kh, kl, 2048);
    gemm_tc<1><<<dim3(128, 4), 256>>>(value, Wv, nullptr, vh, vl, 2048);

    const int smem_bytes = 193280;
    cudaFuncSetAttribute(attn_tc, cudaFuncAttributeMaxDynamicSharedMemorySize,
                         smem_bytes);
    attn_tc<<<dim3(16, 64), 256, smem_bytes>>>(qh, ql, kh, kl, vh, vl, pos,
                                               cptr);

    gemm_tc<0><<<dim3(64, 4), 256>>>(cptr, Wo, out, nullptr, nullptr, 1024);
}

// round 4
// speedup vs baseline: 1.8704x; 1.2333x over previous
#include <cuda_runtime.h>
#include <cuda_bf16.h>
#include <stdint.h>
#include <math.h>

// B=8, M=1024, H=512, K=8 heads, D=64, SPAN=1024, MK=2048
#define DINLINE __device__ __forceinline__

// ---------------- scratch ----------------------------------------------------
__device__ __nv_bfloat16 g_Qh[64 * 1024 * 64];
__device__ __nv_bfloat16 g_Ql[64 * 1024 * 64];
__device__ __nv_bfloat16 g_Kh[64 * 2048 * 64];
__device__ __nv_bfloat16 g_Kl[64 * 2048 * 64];
__device__ __nv_bfloat16 g_Vh[64 * 2048 * 64];
__device__ __nv_bfloat16 g_Vl[64 * 2048 * 64];
__device__ float g_C[8 * 1024 * 512];

// ---------------- helpers ----------------------------------------------------
DINLINE void mma_bf16(float c[4], uint32_t a0, uint32_t a1, uint32_t a2,
                      uint32_t a3, uint32_t b0, uint32_t b1) {
    asm volatile(
        "mma.sync.aligned.m16n8k16.row.col.f32.bf16.bf16.f32 "
        "{%0,%1,%2,%3}, {%4,%5,%6,%7}, {%8,%9}, {%0,%1,%2,%3};\n"
        : "+f"(c[0]), "+f"(c[1]), "+f"(c[2]), "+f"(c[3])
        : "r"(a0), "r"(a1), "r"(a2), "r"(a3), "r"(b0), "r"(b1));
}

DINLINE void split_bf(float x, __nv_bfloat16& h, __nv_bfloat16& l) {
    h = __float2bfloat16_rn(x);
    l = __float2bfloat16_rn(x - __bfloat162float(h));
}

DINLINE void st_bf2(__nv_bfloat16* p, __nv_bfloat16 a, __nv_bfloat16 b) {
    __nv_bfloat162 t;
    t.x = a;
    t.y = b;
    *(__nv_bfloat162*)p = t;
}

// ---------------- bf16x3 GEMM: C[R,512] = A[R,512] @ W[512,512] ---------------
template <int EPI>
__global__ void __launch_bounds__(256, 1) gemm_tc(
    const float* __restrict__ A, const float* __restrict__ W,
    float* __restrict__ outF, __nv_bfloat16* __restrict__ outH,
    __nv_bfloat16* __restrict__ outL, int T) {
    constexpr int AS = 42;
    __shared__ __nv_bfloat16 Ah[128 * AS], Al[128 * AS];
    __shared__ __nv_bfloat16 Bh[128 * AS], Bl[128 * AS];

    const int tid = threadIdx.x;
    const int lane = tid & 31, wid = tid >> 5;
    const int wm = wid >> 2, wn = wid & 3;
    const int row0 = blockIdx.x * 128, col0 = blockIdx.y * 128;
    const int g = lane >> 2, t2 = (lane & 3) * 2;

    float acc[4][4][4] = {};

    for (int kk = 0; kk < 512; kk += 32) {
        {
            int r = tid >> 3, kq = (tid & 7) * 4;
#pragma unroll
            for (int it = 0; it < 4; it++, r += 32) {
                float4 v = *(const float4*)&A[(size_t)(row0 + r) * 512 + kk + kq];
                __nv_bfloat16 h0, l0, h1, l1, h2, l2, h3, l3;
                split_bf(v.x, h0, l0);
                split_bf(v.y, h1, l1);
                split_bf(v.z, h2, l2);
                split_bf(v.w, h3, l3);
                st_bf2(&Ah[r * AS + kq], h0, h1);
                st_bf2(&Ah[r * AS + kq + 2], h2, h3);
                st_bf2(&Al[r * AS + kq], l0, l1);
                st_bf2(&Al[r * AS + kq + 2], l2, l3);
            }
        }
        {
            int k = tid >> 5, c4 = (tid & 31) * 4;
#pragma unroll
            for (int it = 0; it < 4; it++, k += 8) {
                float4 v = *(const float4*)&W[(size_t)(kk + k) * 512 + col0 + c4];
                __nv_bfloat16 h, l;
                split_bf(v.x, h, l); Bh[(c4 + 0) * AS + k] = h; Bl[(c4 + 0) * AS + k] = l;
                split_bf(v.y, h, l); Bh[(c4 + 1) * AS + k] = h; Bl[(c4 + 1) * AS + k] = l;
                split_bf(v.z, h, l); Bh[(c4 + 2) * AS + k] = h; Bl[(c4 + 2) * AS + k] = l;
                split_bf(v.w, h, l); Bh[(c4 + 3) * AS + k] = h; Bl[(c4 + 3) * AS + k] = l;
            }
        }
        __syncthreads();
#pragma unroll
        for (int ks = 0; ks < 32; ks += 16) {
            uint32_t ah[4][4], al[4][4], bh[4][2], bl[4][2];
#pragma unroll
            for (int mf = 0; mf < 4; mf++) {
                int rb = wm * 64 + mf * 16 + g;
                ah[mf][0] = *(uint32_t*)&Ah[rb * AS + ks + t2];
                ah[mf][1] = *(uint32_t*)&Ah[(rb + 8) * AS + ks + t2];
                ah[mf][2] = *(uint32_t*)&Ah[rb * AS + ks + 8 + t2];
                ah[mf][3] = *(uint32_t*)&Ah[(rb + 8) * AS + ks + 8 + t2];
                al[mf][0] = *(uint32_t*)&Al[rb * AS + ks + t2];
                al[mf][1] = *(uint32_t*)&Al[(rb + 8) * AS + ks + t2];
                al[mf][2] = *(uint32_t*)&Al[rb * AS + ks + 8 + t2];
                al[mf][3] = *(uint32_t*)&Al[(rb + 8) * AS + ks + 8 + t2];
            }
#pragma unroll
            for (int nf = 0; nf < 4; nf++) {
                int cb = wn * 32 + nf * 8 + g;
                bh[nf][0] = *(uint32_t*)&Bh[cb * AS + ks + t2];
                bh[nf][1] = *(uint32_t*)&Bh[cb * AS + ks + 8 + t2];
                bl[nf][0] = *(uint32_t*)&Bl[cb * AS + ks + t2];
                bl[nf][1] = *(uint32_t*)&Bl[cb * AS + ks + 8 + t2];
            }
#pragma unroll
            for (int mf = 0; mf < 4; mf++)
#pragma unroll
                for (int nf = 0; nf < 4; nf++) {
                    mma_bf16(acc[mf][nf], ah[mf][0], ah[mf][1], ah[mf][2],
                             ah[mf][3], bh[nf][0], bh[nf][1]);
                    mma_bf16(acc[mf][nf], ah[mf][0], ah[mf][1], ah[mf][2],
                             ah[mf][3], bl[nf][0], bl[nf][1]);
                    mma_bf16(acc[mf][nf], al[mf][0], al[mf][1], al[mf][2],
                             al[mf][3], bh[nf][0], bh[nf][1]);
                }
        }
        __syncthreads();
    }

#pragma unroll
    for (int mf = 0; mf < 4; mf++) {
#pragma unroll
        for (int nf = 0; nf < 4; nf++) {
            int rr = row0 + wm * 64 + mf * 16 + g;
            int cc = col0 + wn * 32 + nf * 8 + t2;
            if (EPI == 0) {
                *(float2*)&outF[(size_t)rr * 512 + cc] =
                    make_float2(acc[mf][nf][0], acc[mf][nf][1]);
                *(float2*)&outF[(size_t)(rr + 8) * 512 + cc] =
                    make_float2(acc[mf][nf][2], acc[mf][nf][3]);
            } else {
                int head = cc >> 6, d = cc & 63;
#pragma unroll
                for (int rh = 0; rh < 2; rh++) {
                    int grow = rr + rh * 8;
                    int b = grow / T, t = grow - b * T;
                    size_t idx = (((size_t)(b * 8 + head) * T + t) << 6) + d;
                    __nv_bfloat16 h0, l0, h1, l1;
                    split_bf(acc[mf][nf][rh * 2 + 0], h0, l0);
                    split_bf(acc[mf][nf][rh * 2 + 1], h1, l1);
                    st_bf2(&outH[idx], h0, h1);
                    st_bf2(&outL[idx], l0, l1);
                }
            }
        }
    }
}

// ---------------- fused banded attention v2 -----------------------------------
// 64 queries/CTA, key-chunk 128 (192 keys loaded), 8 chunks.
// In-register masked softmax; QE via 1 MMA pass (bf16 E, hi-q only).
__global__ void __launch_bounds__(256, 1) attn_tc2(
    const __nv_bfloat16* __restrict__ Qh, const __nv_bfloat16* __restrict__ Ql,
    const __nv_bfloat16* __restrict__ Kh_, const __nv_bfloat16* __restrict__ Kl_,
    const __nv_bfloat16* __restrict__ Vh_, const __nv_bfloat16* __restrict__ Vl_,
    const float* __restrict__ Eg, float* __restrict__ Cg) {
    constexpr int QS = 72, KS = 72, ES = 66, VS = 200, PS = 200, QES = 132;
    extern __shared__ char smraw[];
    __nv_bfloat16* Qsh = (__nv_bfloat16*)smraw;              // [64][QS]
    __nv_bfloat16* Qsl = Qsh + 64 * QS;
    __nv_bfloat16* Ksh = Qsl + 64 * QS;                      // [192][KS]
    __nv_bfloat16* Ksl = Ksh + 192 * KS;
    __nv_bfloat16* Esh = Ksl + 192 * KS;                     // [s=128][ES] hi only
    __nv_bfloat16* Vsh = Esh + 128 * ES;                     // [d=64][VS]
    __nv_bfloat16* Vsl = Vsh + 64 * VS;
    __nv_bfloat16* Psh = Vsl + 64 * VS;                      // [m=64][PS]
    __nv_bfloat16* Psl = Psh + 64 * PS;
    float* QEs = (float*)(Psl + 64 * PS);                    // [64][QES]
    float* redmax = QEs + 64 * QES;                          // [4][64]
    float* redsum = redmax + 256;                            // [4][64]
    float* mrow = redsum + 256;                              // [64]
    float* lrow = mrow + 64;                                 // [64]

    const int tid = threadIdx.x, lane = tid & 31, wid = tid >> 5;
    const int wm = wid >> 2, wn = wid & 3;  // 2 x 4 warps
    const int g = lane >> 2, t2 = (lane & 3) * 2;
    const int n = blockIdx.y, m0 = blockIdx.x * 64;
    const float SCl2 = 0.125f * 1.4426950408889634f;

    // load Q tile (once)
    {
        const uint4* sh = (const uint4*)(Qh + (((size_t)n * 1024 + m0) << 6));
        const uint4* sl = (const uint4*)(Ql + (((size_t)n * 1024 + m0) << 6));
        for (int f = tid; f < 512; f += 256) {
            int m = f >> 3, j = f & 7;
            ((uint4*)(Qsh + m * QS))[j] = sh[f];
            ((uint4*)(Qsl + m * QS))[j] = sl[f];
        }
    }
    if (tid < 64) {
        mrow[tid] = -1e30f;
        lrow[tid] = 0.f;
    }

    float o[2][2][4] = {};

    for (int c = 0; c < 8; c++) {
        const int s0 = c * 128;
        const size_t kbase = ((size_t)n * 2048 + m0 + s0) << 6;
        __syncthreads();  // prior PV / QK reads done before overwrite

        // K chunk: 192 rows x 64 bf16 hi/lo
        {
            const uint4* sh = (const uint4*)(Kh_ + kbase);
            const uint4* sl = (const uint4*)(Kl_ + kbase);
#pragma unroll
            for (int it = 0; it < 6; it++) {
                int f = tid + it * 256;
                int kr = f >> 3, j = f & 7;
                ((uint4*)(Ksh + kr * KS))[j] = sh[f];
                ((uint4*)(Ksl + kr * KS))[j] = sl[f];
            }
        }
        // V chunk transposed: Vs[d][key], 192 keys
        {
            int d2 = tid & 31;
#pragma unroll
            for (int it = 0; it < 12; it++) {
                int key = (((tid >> 5) + it * 8) << 1);
                uint32_t va = *(const uint32_t*)(Vh_ + kbase + (size_t)key * 64 + d2 * 2);
                uint32_t vb = *(const uint32_t*)(Vh_ + kbase + (size_t)(key + 1) * 64 + d2 * 2);
                __nv_bfloat162 a2 = *(__nv_bfloat162*)&va;
                __nv_bfloat162 b2 = *(__nv_bfloat162*)&vb;
                st_bf2(&Vsh[(2 * d2) * VS + key], a2.x, b2.x);
                st_bf2(&Vsh[(2 * d2 + 1) * VS + key], a2.y, b2.y);
                uint32_t wa = *(const uint32_t*)(Vl_ + kbase + (size_t)key * 64 + d2 * 2);
                uint32_t wb = *(const uint32_t*)(Vl_ + kbase + (size_t)(key + 1) * 64 + d2 * 2);
                __nv_bfloat162 c2 = *(__nv_bfloat162*)&wa;
                __nv_bfloat162 e2 = *(__nv_bfloat162*)&wb;
                st_bf2(&Vsl[(2 * d2) * VS + key], c2.x, e2.x);
                st_bf2(&Vsl[(2 * d2 + 1) * VS + key], c2.y, e2.y);
            }
        }
        // E chunk: Esh[s][d] = E[d][s0+s], hi only
#pragma unroll
        for (int it = 0; it < 16; it++) {
            int idx = tid + it * 256;
            int s2 = (idx & 63) * 2, d = idx >> 6;
            float2 e2 = *(const float2*)&Eg[(size_t)d * 1024 + s0 + s2];
            Esh[s2 * ES + d] = __float2bfloat16_rn(e2.x);
            Esh[(s2 + 1) * ES + d] = __float2bfloat16_rn(e2.y);
        }
        __syncthreads();

        // ---- QK (64x192, bf16x3) + QE (64x128, 1 pass) ----
        float sAcc[2][6][4] = {};
        float qeAcc[2][4][4] = {};
#pragma unroll
        for (int ks = 0; ks < 64; ks += 16) {
            uint32_t ah[2][4], al[2][4];
#pragma unroll
            for (int mf = 0; mf < 2; mf++) {
                int rb = wm * 32 + mf * 16 + g;
                ah[mf][0] = *(uint32_t*)&Qsh[rb * QS + ks + t2];
                ah[mf][1] = *(uint32_t*)&Qsh[(rb + 8) * QS + ks + t2];
                ah[mf][2] = *(uint32_t*)&Qsh[rb * QS + ks + 8 + t2];
                ah[mf][3] = *(uint32_t*)&Qsh[(rb + 8) * QS + ks + 8 + t2];
                al[mf][0] = *(uint32_t*)&Qsl[rb * QS + ks + t2];
                al[mf][1] = *(uint32_t*)&Qsl[(rb + 8) * QS + ks + t2];
                al[mf][2] = *(uint32_t*)&Qsl[rb * QS + ks + 8 + t2];
                al[mf][3] = *(uint32_t*)&Qsl[(rb + 8) * QS + ks + 8 + t2];
            }
#pragma unroll
            for (int nf = 0; nf < 6; nf++) {
                int cb = wn * 48 + nf * 8 + g;
                uint32_t kb0 = *(uint32_t*)&Ksh[cb * KS + ks + t2];
                uint32_t kb1 = *(uint32_t*)&Ksh[cb * KS + ks + 8 + t2];
                uint32_t kl0 = *(uint32_t*)&Ksl[cb * KS + ks + t2];
                uint32_t kl1 = *(uint32_t*)&Ksl[cb * KS + ks + 8 + t2];
#pragma unroll
                for (int mf = 0; mf < 2; mf++) {
                    mma_bf16(sAcc[mf][nf], ah[mf][0], ah[mf][1], ah[mf][2],
                             ah[mf][3], kb0, kb1);
                    mma_bf16(sAcc[mf][nf], ah[mf][0], ah[mf][1], ah[mf][2],
                             ah[mf][3], kl0, kl1);
                    mma_bf16(sAcc[mf][nf], al[mf][0], al[mf][1], al[mf][2],
                             al[mf][3], kb0, kb1);
                }
            }
#pragma unroll
            for (int nf = 0; nf < 4; nf++) {
                int cb = wn * 32 + nf * 8 + g;
                uint32_t eb0 = *(uint32_t*)&Esh[cb * ES + ks + t2];
                uint32_t eb1 = *(uint32_t*)&Esh[cb * ES + ks + 8 + t2];
#pragma unroll
                for (int mf = 0; mf < 2; mf++)
                    mma_bf16(qeAcc[mf][nf], ah[mf][0], ah[mf][1], ah[mf][2],
                             ah[mf][3], eb0, eb1);
            }
        }
        // write QE fragments to smem
#pragma unroll
        for (int mf = 0; mf < 2; mf++) {
            int R = wm * 32 + mf * 16 + g;
#pragma unroll
            for (int nf = 0; nf < 4; nf++) {
                int cc = wn * 32 + nf * 8 + t2;
                *(float2*)&QEs[R * QES + cc] =
                    make_float2(qeAcc[mf][nf][0], qeAcc[mf][nf][1]);
                *(float2*)&QEs[(R + 8) * QES + cc] =
                    make_float2(qeAcc[mf][nf][2], qeAcc[mf][nf][3]);
            }
        }
        __syncthreads();

        // ---- phase 1: z = S + QE (masked), per-warp row max partials ----
#pragma unroll
        for (int mf = 0; mf < 2; mf++) {
            int R = wm * 32 + mf * 16 + g;
            float mx0 = -3e38f, mx1 = -3e38f;
#pragma unroll
            for (int nf = 0; nf < 6; nf++) {
                int cc = wn * 48 + nf * 8 + t2;
#pragma unroll
                for (int e = 0; e < 4; e++) {
                    int r = R + (e >> 1) * 8;
                    int col = cc + (e & 1);
                    int diff = col - r;
                    float z;
                    if ((unsigned)diff < 128u)
                        z = sAcc[mf][nf][e] + QEs[r * QES + diff];
                    else
                        z = -3e38f;
                    sAcc[mf][nf][e] = z;
                    if (e < 2) mx0 = fmaxf(mx0, z);
                    else mx1 = fmaxf(mx1, z);
                }
            }
            mx0 = fmaxf(mx0, __shfl_xor_sync(0xffffffffu, mx0, 1));
            mx0 = fmaxf(mx0, __shfl_xor_sync(0xffffffffu, mx0, 2));
            mx1 = fmaxf(mx1, __shfl_xor_sync(0xffffffffu, mx1, 1));
            mx1 = fmaxf(mx1, __shfl_xor_sync(0xffffffffu, mx1, 2));
            if ((lane & 3) == 0) {
                redmax[wn * 64 + R] = mx0;
                redmax[wn * 64 + R + 8] = mx1;
            }
        }
        __syncthreads();

        // ---- phase 2: full row max, exp, P store, sum partials, O rescale ----
        float mn[2][2], alpha[2][2];
#pragma unroll
        for (int mf = 0; mf < 2; mf++) {
            int R = wm * 32 + mf * 16 + g;
#pragma unroll
            for (int h = 0; h < 2; h++) {
                int r = R + h * 8;
                float rm = fmaxf(fmaxf(redmax[r], redmax[64 + r]),
                                 fmaxf(redmax[128 + r], redmax[192 + r]));
                float mo = mrow[r];
                float m2 = fmaxf(mo, rm * SCl2);
                mn[mf][h] = m2;
                alpha[mf][h] = exp2f(mo - m2);
            }
        }
#pragma unroll
        for (int mf = 0; mf < 2; mf++) {
            int R = wm * 32 + mf * 16 + g;
            float sum0 = 0.f, sum1 = 0.f;
#pragma unroll
            for (int nf = 0; nf < 6; nf++) {
                int cc = wn * 48 + nf * 8 + t2;
                float p[4];
#pragma unroll
                for (int e = 0; e < 4; e++) {
                    int r = R + (e >> 1) * 8;
                    int col = cc + (e & 1);
                    int diff = col - r;
                    float pv = 0.f;
                    if ((unsigned)diff < 128u)
                        pv = exp2f(sAcc[mf][nf][e] * SCl2 - mn[mf][e >> 1]);
                    p[e] = pv;
                    if (e < 2) sum0 += pv;
                    else sum1 += pv;
                }
                __nv_bfloat16 h0, l0, h1, l1;
                split_bf(p[0], h0, l0);
                split_bf(p[1], h1, l1);
                st_bf2(&Psh[R * PS + cc], h0, h1);
                st_bf2(&Psl[R * PS + cc], l0, l1);
                split_bf(p[2], h0, l0);
                split_bf(p[3], h1, l1);
                st_bf2(&Psh[(R + 8) * PS + cc], h0, h1);
                st_bf2(&Psl[(R + 8) * PS + cc], l0, l1);
            }
            sum0 += __shfl_xor_sync(0xffffffffu, sum0, 1);
            sum0 += __shfl_xor_sync(0xffffffffu, sum0, 2);
            sum1 += __shfl_xor_sync(0xffffffffu, sum1, 1);
            sum1 += __shfl_xor_sync(0xffffffffu, sum1, 2);
            if ((lane & 3) == 0) {
                redsum[wn * 64 + R] = sum0;
                redsum[wn * 64 + R + 8] = sum1;
            }
            // rescale O for these rows
#pragma unroll
            for (int nf = 0; nf < 2; nf++) {
                o[mf][nf][0] *= alpha[mf][0];
                o[mf][nf][1] *= alpha[mf][0];
                o[mf][nf][2] *= alpha[mf][1];
                o[mf][nf][3] *= alpha[mf][1];
            }
        }
        __syncthreads();

        // state update (one thread per row)
        if (wn == 0 && (lane & 3) == 0) {
#pragma unroll
            for (int mf = 0; mf < 2; mf++) {
                int R = wm * 32 + mf * 16 + g;
#pragma unroll
                for (int h = 0; h < 2; h++) {
                    int r = R + h * 8;
                    float s = redsum[r] + redsum[64 + r] + redsum[128 + r] +
                              redsum[192 + r];
                    lrow[r] = lrow[r] * alpha[mf][h] + s;
                    mrow[r] = mn[mf][h];
                }
            }
        }

        // ---- PV: O += P(64x192) @ V^T(192x64) ----
#pragma unroll
        for (int ks = 0; ks < 192; ks += 16) {
            uint32_t ph[2][4], pl[2][4];
#pragma unroll
            for (int mf = 0; mf < 2; mf++) {
                int rb = wm * 32 + mf * 16 + g;
                ph[mf][0] = *(uint32_t*)&Psh[rb * PS + ks + t2];
                ph[mf][1] = *(uint32_t*)&Psh[(rb + 8) * PS + ks + t2];
                ph[mf][2] = *(uint32_t*)&Psh[rb * PS + ks + 8 + t2];
                ph[mf][3] = *(uint32_t*)&Psh[(rb + 8) * PS + ks + 8 + t2];
                pl[mf][0] = *(uint32_t*)&Psl[rb * PS + ks + t2];
                pl[mf][1] = *(uint32_t*)&Psl[(rb + 8) * PS + ks + t2];
                pl[mf][2] = *(uint32_t*)&Psl[rb * PS + ks + 8 + t2];
                pl[mf][3] = *(uint32_t*)&Psl[(rb + 8) * PS + ks + 8 + t2];
            }
#pragma unroll
            for (int nf = 0; nf < 2; nf++) {
                int cb = wn * 16 + nf * 8 + g;
                uint32_t vh0 = *(uint32_t*)&Vsh[cb * VS + ks + t2];
                uint32_t vh1 = *(uint32_t*)&Vsh[cb * VS + ks + 8 + t2];
                uint32_t vl0 = *(uint32_t*)&Vsl[cb * VS + ks + t2];
                uint32_t vl1 = *(uint32_t*)&Vsl[cb * VS + ks + 8 + t2];
#pragma unroll
                for (int mf = 0; mf < 2; mf++) {
                    mma_bf16(o[mf][nf], ph[mf][0], ph[mf][1], ph[mf][2],
                             ph[mf][3], vh0, vh1);
                    mma_bf16(o[mf][nf], ph[mf][0], ph[mf][1], ph[mf][2],
                             ph[mf][3], vl0, vl1);
                    mma_bf16(o[mf][nf], pl[mf][0], pl[mf][1], pl[mf][2],
                             pl[mf][3], vh0, vh1);
                }
            }
        }
    }

    __syncthreads();
    // epilogue
    const int b = n >> 3, kh = n & 7;
#pragma unroll
    for (int mf = 0; mf < 2; mf++) {
        int r = wm * 32 + mf * 16 + g;
        float i0 = 1.0f / lrow[r];
        float i1 = 1.0f / lrow[r + 8];
#pragma unroll
        for (int nf = 0; nf < 2; nf++) {
            int cc = kh * 64 + wn * 16 + nf * 8 + t2;
            size_t base = ((size_t)b * 1024 + m0 + r) * 512 + cc;
            *(float2*)&Cg[base] =
                make_float2(o[mf][nf][0] * i0, o[mf][nf][1] * i0);
            *(float2*)&Cg[base + 8 * 512] =
                make_float2(o[mf][nf][2] * i1, o[mf][nf][3] * i1);
        }
    }
}

// ---------------- launcher ----------------------------------------------------
extern "C" void kernel_launch(void* const* d_in, const int* in_sizes, int n_in,
                              void* d_out, int out_size) {
    const float* query = (const float*)d_in[0];
    const float* key = (const float*)d_in[1];
    const float* value = (const float*)d_in[2];
    const float* pos = (const float*)d_in[3];
    const float* Wq = (const float*)d_in[4];
    const float* Wk = (const float*)d_in[5];
    const float* Wv = (const float*)d_in[6];
    const float* Wo = (const float*)d_in[7];
    float* out = (float*)d_out;

    __nv_bfloat16 *qh, *ql, *kh, *kl, *vh, *vl;
    float* cptr;
    cudaGetSymbolAddress((void**)&qh, g_Qh);
    cudaGetSymbolAddress((void**)&ql, g_Ql);
    cudaGetSymbolAddress((void**)&kh, g_Kh);
    cudaGetSymbolAddress((void**)&kl, g_Kl);
    cudaGetSymbolAddress((void**)&vh, g_Vh);
    cudaGetSymbolAddress((void**)&vl, g_Vl);
    cudaGetSymbolAddress((void**)&cptr, g_C);

    gemm_tc<1><<<dim3(64, 4), 256>>>(query, Wq, nullptr, qh, ql, 1024);
    gemm_tc<1><<<dim3(128, 4), 256>>>(key, Wk, nullptr, kh, kl, 2048);
    gemm_tc<1><<<dim3(128, 4), 256>>>(value, Wv, nullptr, vh, vl, 2048);

    // smem: bf16 regions + fp32 regions
    const int smem_bytes =
        (2 * 64 * 72 + 2 * 192 * 72 + 128 * 66 + 2 * 64 * 200 + 2 * 64 * 200) * 2 +
        (64 * 132 + 256 + 256 + 64 + 64) * 4;
    cudaFuncSetAttribute(attn_tc2, cudaFuncAttributeMaxDynamicSharedMemorySize,
                         smem_bytes);
    attn_tc2<<<dim3(16, 64), 256, smem_bytes>>>(qh, ql, kh, kl, vh, vl, pos,
                                                cptr);

    gemm_tc<0><<<dim3(64, 4), 256>>>(cptr, Wo, out, nullptr, nullptr, 1024);
}